// round 7
// baseline (speedup 1.0000x reference)
#include <cuda_runtime.h>
#include <cuda_bf16.h>

#define D_MODEL 2048
#define RANK    64
#define VOCAB   50257
#define N_TOK   32

#define NBLK_PART 32          // 32 blocks x 64 d-rows each

__device__ float g_part[NBLK_PART * N_TOK];  // per-block partials
__device__ float g_s[N_TOK];                 // final s[n]
__device__ int   g_count;                    // zero-initialized; self-resetting

// Kernel 1: partial s over d-slice; last block folds partials into g_s.
__global__ __launch_bounds__(256)
void fftlm_partial_kernel(const float* __restrict__ h,
                          const float* __restrict__ U,
                          const float* __restrict__ S) {
    __shared__ float sS[RANK];
    __shared__ float su[64];
    __shared__ int   is_last;

    const int tid  = threadIdx.x;
    const int warp = tid >> 5;
    const int lane = tid & 31;
    const int dbase = blockIdx.x * 64;

    if (tid < RANK) sS[tid] = S[tid];
    __syncthreads();

#pragma unroll
    for (int k = 0; k < 8; k++) {
        int dl = warp * 8 + k;
        const float* Ur = U + (size_t)(dbase + dl) * RANK;
        float v = Ur[lane] * sS[lane] + Ur[lane + 32] * sS[lane + 32];
#pragma unroll
        for (int o = 16; o; o >>= 1) v += __shfl_xor_sync(0xffffffffu, v, o);
        if (lane == 0) su[dl] = v;
    }
    __syncthreads();

#pragma unroll
    for (int k = 0; k < 4; k++) {
        int n = warp * 4 + k;
        const float* hr = h + (size_t)n * D_MODEL + dbase;
        float v = hr[lane] * su[lane] + hr[lane + 32] * su[lane + 32];
#pragma unroll
        for (int o = 16; o; o >>= 1) v += __shfl_xor_sync(0xffffffffu, v, o);
        if (lane == 0) g_part[blockIdx.x * N_TOK + n] = v;
    }

    __threadfence();
    if (tid == 0) is_last = (atomicAdd(&g_count, 1) == NBLK_PART - 1);
    __syncthreads();
    if (is_last) {
        if (tid < N_TOK) {
            float acc = 0.f;
#pragma unroll
            for (int b = 0; b < NBLK_PART; b++) acc += g_part[b * N_TOK + tid];
            g_s[tid] = acc;
        }
        if (tid == 0) g_count = 0;   // self-reset for next graph replay
    }
}

// Kernel 2: out[n, v] = s[n] * (sum_r Vh[r, v])
// One thread per column. All 64 rank loads issued as a single batch of
// independent LDGs using TWO base pointers + compile-time immediate offsets
// (i*VOCAB*4 <= 6.2MB, inside the LDG imm range) -> MLP = 64 per thread.
__global__ __launch_bounds__(64)
void fftlm_outer_kernel(const float* __restrict__ Vh,
                        float* __restrict__ out) {
    __shared__ float s_sh[N_TOK];
    if (threadIdx.x < N_TOK) s_sh[threadIdx.x] = g_s[threadIdx.x];
    __syncthreads();

    const int col = blockIdx.x * 64 + threadIdx.x;
    if (col >= VOCAB) return;

    const float* p0 = Vh + col;                      // rows 0..31
    const float* p1 = Vh + (size_t)32 * VOCAB + col; // rows 32..63

    float buf[64];
    // issue all 64 loads before consuming any — imm offsets from 2 bases
#pragma unroll
    for (int i = 0; i < 32; i++) buf[i]      = p0[(size_t)i * VOCAB];
#pragma unroll
    for (int i = 0; i < 32; i++) buf[32 + i] = p1[(size_t)i * VOCAB];

    // pairwise tree sum (keeps the adds off the load critical path)
#pragma unroll
    for (int stride = 32; stride >= 1; stride >>= 1)
#pragma unroll
        for (int i = 0; i < stride; i++) buf[i] += buf[i + stride];
    const float acc = buf[0];

    float* q = out + col;
#pragma unroll
    for (int n = 0; n < N_TOK; n++)
        q[(size_t)n * VOCAB] = s_sh[n] * acc;
}

extern "C" void kernel_launch(void* const* d_in, const int* in_sizes, int n_in,
                              void* d_out, int out_size) {
    const float* h  = (const float*)d_in[0];  // (32, 2048)
    const float* U  = (const float*)d_in[1];  // (2048, 64)
    const float* S  = (const float*)d_in[2];  // (64,)
    const float* Vh = (const float*)d_in[3];  // (64, 50257)
    float* out = (float*)d_out;               // (32, 50257)

    fftlm_partial_kernel<<<NBLK_PART, 256>>>(h, U, S);

    const int blocks = (VOCAB + 63) / 64;     // 786
    fftlm_outer_kernel<<<blocks, 64>>>(Vh, out);
}

// round 8
// speedup vs baseline: 1.0652x; 1.0652x over previous
#include <cuda_runtime.h>
#include <cuda_bf16.h>

#define D_MODEL 2048
#define RANK    64
#define VOCAB   50257
#define N_TOK   32

#define NBLK_PART 32          // 32 blocks x 64 d-rows each

__device__ float g_part[NBLK_PART * N_TOK];  // per-block partials
__device__ float g_s[N_TOK];                 // final s[n]
__device__ int   g_count;                    // zero-initialized; self-resetting

// Kernel 1: partial s over d-slice; last block folds partials into g_s.
__global__ __launch_bounds__(256)
void fftlm_partial_kernel(const float* __restrict__ h,
                          const float* __restrict__ U,
                          const float* __restrict__ S) {
    __shared__ float sS[RANK];
    __shared__ float su[64];
    __shared__ int   is_last;

    const int tid  = threadIdx.x;
    const int warp = tid >> 5;
    const int lane = tid & 31;
    const int dbase = blockIdx.x * 64;

    if (tid < RANK) sS[tid] = S[tid];
    __syncthreads();

#pragma unroll
    for (int k = 0; k < 8; k++) {
        int dl = warp * 8 + k;
        const float* Ur = U + (size_t)(dbase + dl) * RANK;
        float v = Ur[lane] * sS[lane] + Ur[lane + 32] * sS[lane + 32];
#pragma unroll
        for (int o = 16; o; o >>= 1) v += __shfl_xor_sync(0xffffffffu, v, o);
        if (lane == 0) su[dl] = v;
    }
    __syncthreads();

#pragma unroll
    for (int k = 0; k < 4; k++) {
        int n = warp * 4 + k;
        const float* hr = h + (size_t)n * D_MODEL + dbase;
        float v = hr[lane] * su[lane] + hr[lane + 32] * su[lane + 32];
#pragma unroll
        for (int o = 16; o; o >>= 1) v += __shfl_xor_sync(0xffffffffu, v, o);
        if (lane == 0) g_part[blockIdx.x * N_TOK + n] = v;
    }

    __threadfence();
    if (tid == 0) is_last = (atomicAdd(&g_count, 1) == NBLK_PART - 1);
    __syncthreads();
    if (is_last) {
        if (tid < N_TOK) {
            float acc = 0.f;
#pragma unroll
            for (int b = 0; b < NBLK_PART; b++) acc += g_part[b * N_TOK + tid];
            g_s[tid] = acc;
        }
        if (tid == 0) g_count = 0;   // self-reset for next graph replay
    }
}

// Kernel 2: out[n, v] = s[n] * (sum_r Vh[r, v])
// One thread per column. CRITICAL: __launch_bounds__(128, 2) grants ~256 regs
// per thread so the 64-load staging batch stays LIVE (prior rounds ptxas was
// capped at 32 regs by the occupancy heuristic and serialized the loads).
__global__ __launch_bounds__(128, 2)
void fftlm_outer_kernel(const float* __restrict__ Vh,
                        float* __restrict__ out) {
    __shared__ float s_sh[N_TOK];
    if (threadIdx.x < N_TOK) s_sh[threadIdx.x] = g_s[threadIdx.x];
    __syncthreads();

    const int col = blockIdx.x * 128 + threadIdx.x;
    if (col >= VOCAB) return;

    const float* p0 = Vh + col;                      // rows 0..31
    const float* p1 = Vh + (size_t)32 * VOCAB + col; // rows 32..63

    float buf[64];
    // issue all 64 loads before consuming any — imm offsets from 2 bases
#pragma unroll
    for (int i = 0; i < 32; i++) buf[i]      = p0[(size_t)i * VOCAB];
#pragma unroll
    for (int i = 0; i < 32; i++) buf[32 + i] = p1[(size_t)i * VOCAB];

    // pairwise tree sum
#pragma unroll
    for (int stride = 32; stride >= 1; stride >>= 1)
#pragma unroll
        for (int i = 0; i < stride; i++) buf[i] += buf[i + stride];
    const float acc = buf[0];

    float* q = out + col;
#pragma unroll
    for (int n = 0; n < N_TOK; n++)
        q[(size_t)n * VOCAB] = s_sh[n] * acc;
}

extern "C" void kernel_launch(void* const* d_in, const int* in_sizes, int n_in,
                              void* d_out, int out_size) {
    const float* h  = (const float*)d_in[0];  // (32, 2048)
    const float* U  = (const float*)d_in[1];  // (2048, 64)
    const float* S  = (const float*)d_in[2];  // (64,)
    const float* Vh = (const float*)d_in[3];  // (64, 50257)
    float* out = (float*)d_out;               // (32, 50257)

    fftlm_partial_kernel<<<NBLK_PART, 256>>>(h, U, S);

    const int blocks = (VOCAB + 127) / 128;   // 393
    fftlm_outer_kernel<<<blocks, 128>>>(Vh, out);
}